// round 11
// baseline (speedup 1.0000x reference)
#include <cuda_runtime.h>

// x: (B=16, L=8192, F=512) float32, contiguous.
// y[b,t,:] = x[b,t+1,:] - x[b,t,:]   for t < L-1
// y[b,L-1,:] = x[b,L-1,:] - x[b,L-2,:]
//
// R3 config exactly (best measured: ITEMS=4, 256 threads, front-batched
// loads, MLP_p1=8, regs ~34, occ ~63%), plus ONE change: __stcs on the
// output stores (evict-first — y is write-once, keep L2 ways for the
// x reuse window).

static constexpr int F4_PER_ROW = 512 / 4;   // 128
static constexpr int L_STEPS    = 8192;
static constexpr int ITEMS      = 4;
static constexpr int THREADS    = 256;

__global__ void __launch_bounds__(THREADS)
diff1d_kernel(const float4* __restrict__ x, float4* __restrict__ y, int n4)
{
    int base = blockIdx.x * (THREADS * ITEMS) + threadIdx.x;

    int    jj[ITEMS];
    float  ss[ITEMS];
    float4 a[ITEMS];
    float4 b[ITEMS];

    // Index math + front-batched loads (8 independent LDG.128)
    #pragma unroll
    for (int i = 0; i < ITEMS; i++) {
        int j     = base + i * THREADS;
        int t     = (j >> 7) & (L_STEPS - 1);
        bool last = (t == L_STEPS - 1);
        int jb    = j + (last ? -F4_PER_ROW : F4_PER_ROW);
        jj[i]     = j;
        ss[i]     = last ? -1.0f : 1.0f;
        a[i]      = x[j];
        b[i]      = x[jb];
    }

    #pragma unroll
    for (int i = 0; i < ITEMS; i++) {
        float4 r;
        r.x = ss[i] * (b[i].x - a[i].x);
        r.y = ss[i] * (b[i].y - a[i].y);
        r.z = ss[i] * (b[i].z - a[i].z);
        r.w = ss[i] * (b[i].w - a[i].w);
        __stcs(&y[jj[i]], r);        // evict-first: y is write-once
    }
}

extern "C" void kernel_launch(void* const* d_in, const int* in_sizes, int n_in,
                              void* d_out, int out_size)
{
    const float4* x = (const float4*)d_in[0];
    float4* y = (float4*)d_out;
    int n4 = out_size / 4;               // 16,777,216 float4

    int tile   = THREADS * ITEMS;        // 1024 float4 per block
    int blocks = (n4 + tile - 1) / tile; // 16384, exact
    diff1d_kernel<<<blocks, THREADS>>>(x, y, n4);
}

// round 12
// speedup vs baseline: 1.0055x; 1.0055x over previous
#include <cuda_runtime.h>

// x: (B=16, L=8192, F=512) float32, contiguous.
// y[b,t,:] = x[b,t+1,:] - x[b,t,:]   for t < L-1
// y[b,L-1,:] = x[b,L-1,:] - x[b,L-2,:]
//
// Final kernel == R3 (best measured: 74.4us kernel, DRAM 81.7%).
// float4-vectorized, ITEMS=4 per thread, front-batched loads (8 independent
// LDG.128, MLP_p1=8), branchless edge handling via sign flip, default
// cache policy (both .CS hints measured as regressions on sm_103a).

static constexpr int F4_PER_ROW = 512 / 4;   // 128
static constexpr int L_STEPS    = 8192;
static constexpr int ITEMS      = 4;
static constexpr int THREADS    = 256;

__global__ void __launch_bounds__(THREADS)
diff1d_kernel(const float4* __restrict__ x, float4* __restrict__ y, int n4)
{
    int base = blockIdx.x * (THREADS * ITEMS) + threadIdx.x;

    int    jj[ITEMS];
    float  ss[ITEMS];
    float4 a[ITEMS];
    float4 b[ITEMS];

    // Index math + front-batched loads (8 independent LDG.128)
    #pragma unroll
    for (int i = 0; i < ITEMS; i++) {
        int j     = base + i * THREADS;
        int t     = (j >> 7) & (L_STEPS - 1);
        bool last = (t == L_STEPS - 1);
        int jb    = j + (last ? -F4_PER_ROW : F4_PER_ROW);
        jj[i]     = j;
        ss[i]     = last ? -1.0f : 1.0f;
        a[i]      = x[j];
        b[i]      = x[jb];
    }

    #pragma unroll
    for (int i = 0; i < ITEMS; i++) {
        float4 r;
        r.x = ss[i] * (b[i].x - a[i].x);
        r.y = ss[i] * (b[i].y - a[i].y);
        r.z = ss[i] * (b[i].z - a[i].z);
        r.w = ss[i] * (b[i].w - a[i].w);
        y[jj[i]] = r;
    }
}

extern "C" void kernel_launch(void* const* d_in, const int* in_sizes, int n_in,
                              void* d_out, int out_size)
{
    const float4* x = (const float4*)d_in[0];
    float4* y = (float4*)d_out;
    int n4 = out_size / 4;               // 16,777,216 float4

    int tile   = THREADS * ITEMS;        // 1024 float4 per block
    int blocks = (n4 + tile - 1) / tile; // 16384, exact
    diff1d_kernel<<<blocks, THREADS>>>(x, y, n4);
}